// round 16
// baseline (speedup 1.0000x reference)
#include <cuda_runtime.h>
#include <cuda_fp16.h>
#include <cstdint>

#define NN 50000
#define EE 800000
#define F  64
#define NG 64
#define CAP 64          // per-node neighbor bucket capacity (max degree ~45, +3 pad)

// ---------------- scratch (device globals) ----------------------------------
__device__ __half g_pinh [(NN + 1) * F];   // row NN = zero row (pad target)
__device__ __half g_pouth[(NN + 1) * F];
__device__ float  g_h    [NN * F];
__device__ float  g_pool [NG * F];
__device__ float  g_cnt  [NG];

__device__ int g_cntin [NN];
__device__ int g_cntout[NN];
__device__ int g_bin [NN * CAP];
__device__ int g_bout[NN * CAP];

__device__ __forceinline__ unsigned h2_as_u(__half2 h) {
    return *reinterpret_cast<unsigned*>(&h);
}
__device__ __forceinline__ __half2 u_as_h2(unsigned u) {
    return *reinterpret_cast<__half2*>(&u);
}
// packed f32x2 FMA: d = a*b + d  (PTX ISA 8.6+, sm_100+)
__device__ __forceinline__ void ffma2(unsigned long long& d,
                                      unsigned long long a, unsigned long long b) {
    asm("fma.rn.f32x2 %0, %1, %2, %0;" : "+l"(d) : "l"(a), "l"(b));
}
__device__ __forceinline__ unsigned long long dup_f32(float x) {
    unsigned long long r;
    asm("mov.b64 %0, {%1, %1};" : "=l"(r) : "f"(x));
    return r;
}
__device__ __forceinline__ float2 unpack_f32x2(unsigned long long v) {
    float2 f;
    asm("mov.b64 {%0, %1}, %2;" : "=f"(f.x), "=f"(f.y) : "l"(v));
    return f;
}

// ---------------- init -------------------------------------------------------
__global__ void k_init(int n) {
    int t = blockIdx.x * blockDim.x + threadIdx.x;
    if (t < n) { g_cntin[t] = 0; g_cntout[t] = 0; }
    if (t < NG * F) g_pool[t] = 0.0f;
    if (t < NG) g_cnt[t] = 0.0f;
    if (t < F) {                         // zero row for bucket padding
        g_pinh [NN * F + t] = __ushort_as_half(0);
        g_pouth[NN * F + t] = __ushort_as_half(0);
    }
}

// ---------------- fused bucket build: 1 pass, rank = atomic return ----------
__global__ void k_build(const int* __restrict__ src, const int* __restrict__ dst, int e) {
    int t = blockIdx.x * blockDim.x + threadIdx.x;
    int i = t * 2;
    if (i + 1 < e) {
        int2 s2 = ((const int2*)src)[t];
        int2 d2 = ((const int2*)dst)[t];
        int r0 = atomicAdd(&g_cntin [d2.x], 1);
        int r1 = atomicAdd(&g_cntin [d2.y], 1);
        int q0 = atomicAdd(&g_cntout[s2.x], 1);
        int q1 = atomicAdd(&g_cntout[s2.y], 1);
        g_bin [d2.x * CAP + r0] = s2.x;
        g_bin [d2.y * CAP + r1] = s2.y;
        g_bout[s2.x * CAP + q0] = d2.x;
        g_bout[s2.y * CAP + q1] = d2.y;
    } else if (i < e) {
        int s = src[i], d = dst[i];
        int r = atomicAdd(&g_cntin [d], 1); g_bin [d * CAP + r] = s;
        int q = atomicAdd(&g_cntout[s], 1); g_bout[s * CAP + q] = d;
    }
}

// ---------------- pad buckets to quad boundary with zero-row index ----------
__global__ void k_pad(int n) {
    int t = blockIdx.x * blockDim.x + threadIdx.x;
    if (t >= n) return;
    int c = g_cntin[t];
    int r = (c + 3) & ~3;
    for (int j = c; j < r; j++) g_bin[t * CAP + j] = NN;
    c = g_cntout[t];
    r = (c + 3) & ~3;
    for (int j = c; j < r; j++) g_bout[t * CAP + j] = NN;
}

// ---------------- fused dual GEMM: 8 rows/thread, fp16 xs, f32x2 FFMA -------
__global__ __launch_bounds__(256) void k_gemm(const float* __restrict__ xin,
                                              const float* __restrict__ Win,
                                              const float* __restrict__ Wout,
                                              int n) {
    __shared__ unsigned xs[128 * 32];    // fp16x2: 128 rows x 32 half2 = 16 KB
    __shared__ float wi[64 * 64];        // 16 KB
    __shared__ float wo[64 * 64];        // 16 KB
    const float* x = xin ? xin : g_h;

    int tid = threadIdx.x;
    {
        float4* wi4 = (float4*)wi; const float4* Wi4 = (const float4*)Win;
        float4* wo4 = (float4*)wo; const float4* Wo4 = (const float4*)Wout;
        #pragma unroll
        for (int i = tid; i < 1024; i += 256) { wi4[i] = Wi4[i]; wo4[i] = Wo4[i]; }
    }
    int base = blockIdx.x * 128;
    {
        const float4* x4 = (const float4*)x;
        #pragma unroll
        for (int i = tid; i < 2048; i += 256) {
            int r = i >> 4, c = i & 15;
            int row = base + r;
            float4 v = (row < n) ? x4[row * 16 + c] : make_float4(0.f, 0.f, 0.f, 0.f);
            uint2 u;
            u.x = h2_as_u(__float22half2_rn(make_float2(v.x, v.y)));
            u.y = h2_as_u(__float22half2_rn(make_float2(v.z, v.w)));
            ((uint2*)xs)[r * 16 + c] = u;
        }
    }
    __syncthreads();

    int fq = tid & 15;
    int rg = tid >> 4;
    int r0 = rg * 8;

    unsigned long long ai[8][2], ao[8][2];
    #pragma unroll
    for (int r = 0; r < 8; r++) {
        ai[r][0] = 0ull; ai[r][1] = 0ull;
        ao[r][0] = 0ull; ao[r][1] = 0ull;
    }
    const ulonglong2* wi2 = (const ulonglong2*)wi;
    const ulonglong2* wo2 = (const ulonglong2*)wo;
    #pragma unroll 4
    for (int kp = 0; kp < 32; kp++) {            // k-pairs
        ulonglong2 wa0 = wi2[(kp * 2 + 0) * 16 + fq];
        ulonglong2 wb0 = wo2[(kp * 2 + 0) * 16 + fq];
        ulonglong2 wa1 = wi2[(kp * 2 + 1) * 16 + fq];
        ulonglong2 wb1 = wo2[(kp * 2 + 1) * 16 + fq];
        #pragma unroll
        for (int r = 0; r < 8; r++) {
            float2 xf = __half22float2(u_as_h2(xs[(r0 + r) * 32 + kp]));
            unsigned long long x0 = dup_f32(xf.x);
            unsigned long long x1 = dup_f32(xf.y);
            ffma2(ai[r][0], x0, wa0.x);
            ffma2(ai[r][1], x0, wa0.y);
            ffma2(ao[r][0], x0, wb0.x);
            ffma2(ao[r][1], x0, wb0.y);
            ffma2(ai[r][0], x1, wa1.x);
            ffma2(ai[r][1], x1, wa1.y);
            ffma2(ao[r][0], x1, wb1.x);
            ffma2(ao[r][1], x1, wb1.y);
        }
    }
    #pragma unroll
    for (int r = 0; r < 8; r++) {
        int row = base + r0 + r;
        if (row >= n) break;
        float di = rsqrtf(1.0f + (float)g_cntin [row]);
        float dq = rsqrtf(1.0f + (float)g_cntout[row]);
        float2 i01 = unpack_f32x2(ai[r][0]), i23 = unpack_f32x2(ai[r][1]);
        float2 o01 = unpack_f32x2(ao[r][0]), o23 = unpack_f32x2(ao[r][1]);
        __half2 pi0 = __float22half2_rn(make_float2(i01.x * di, i01.y * di));
        __half2 pi1 = __float22half2_rn(make_float2(i23.x * di, i23.y * di));
        __half2 po0 = __float22half2_rn(make_float2(o01.x * dq, o01.y * dq));
        __half2 po1 = __float22half2_rn(make_float2(o23.x * dq, o23.y * dq));
        uint2 ui, uo;
        ui.x = h2_as_u(pi0); ui.y = h2_as_u(pi1);
        uo.x = h2_as_u(po0); uo.y = h2_as_u(po1);
        ((uint2*)g_pinh )[row * 16 + fq] = ui;
        ((uint2*)g_pouth)[row * 16 + fq] = uo;
    }
}

// ---------------- gather: padded quads, straight-line inner loop ------------
__global__ __launch_bounds__(256) void k_gather(const float* __restrict__ bin,
                                                const float* __restrict__ bout,
                                                int n, int doRelu) {
    int v = (blockIdx.x * 256 + threadIdx.x) >> 5;
    if (v >= n) return;
    int lane = threadIdx.x & 31;
    int fq   = lane & 15;
    int half = lane >> 4;
    const uint2* pin2  = (const uint2*)g_pinh;
    const uint2* pout2 = (const uint2*)g_pouth;

    __half2 z = u_as_h2(0u);
    __half2 a0x = z, a0y = z, a1x = z, a1y = z;
    __half2 b0x = z, b0y = z, b1x = z, b1y = z;

    if (half == 0) {
        uint2 s = pin2[v * 16 + fq];
        a0x = u_as_h2(s.x); a0y = u_as_h2(s.y);
        uint2 t = pout2[v * 16 + fq];
        b0x = u_as_h2(t.x); b0y = u_as_h2(t.y);
    }

    int cA = g_cntin [v];
    int cB = g_cntout[v];
    const int4* binA = (const int4*)(g_bin  + v * CAP);
    const int4* binB = (const int4*)(g_bout + v * CAP);

    int nqA = (cA + 3) >> 2;
    #pragma unroll 4
    for (int j = 0; j < nqA; j++) {
        int4 i4 = binA[j];
        int e0 = half ? i4.y : i4.x;
        int e1 = half ? i4.w : i4.z;
        uint2 m0 = pin2[e0 * 16 + fq];
        uint2 m1 = pin2[e1 * 16 + fq];
        a0x = __hadd2(a0x, u_as_h2(m0.x)); a0y = __hadd2(a0y, u_as_h2(m0.y));
        a1x = __hadd2(a1x, u_as_h2(m1.x)); a1y = __hadd2(a1y, u_as_h2(m1.y));
    }

    int nqB = (cB + 3) >> 2;
    #pragma unroll 4
    for (int j = 0; j < nqB; j++) {
        int4 i4 = binB[j];
        int e0 = half ? i4.y : i4.x;
        int e1 = half ? i4.w : i4.z;
        uint2 m0 = pout2[e0 * 16 + fq];
        uint2 m1 = pout2[e1 * 16 + fq];
        b0x = __hadd2(b0x, u_as_h2(m0.x)); b0y = __hadd2(b0y, u_as_h2(m0.y));
        b1x = __hadd2(b1x, u_as_h2(m1.x)); b1y = __hadd2(b1y, u_as_h2(m1.y));
    }

    float2 p0, p1;
    float4 ain, aout;
    p0 = __half22float2(a0x); p1 = __half22float2(a1x);
    ain.x = p0.x + p1.x; ain.y = p0.y + p1.y;
    p0 = __half22float2(a0y); p1 = __half22float2(a1y);
    ain.z = p0.x + p1.x; ain.w = p0.y + p1.y;
    p0 = __half22float2(b0x); p1 = __half22float2(b1x);
    aout.x = p0.x + p1.x; aout.y = p0.y + p1.y;
    p0 = __half22float2(b0y); p1 = __half22float2(b1y);
    aout.z = p0.x + p1.x; aout.w = p0.y + p1.y;

    ain.x  += __shfl_xor_sync(0xffffffffu, ain.x,  16);
    ain.y  += __shfl_xor_sync(0xffffffffu, ain.y,  16);
    ain.z  += __shfl_xor_sync(0xffffffffu, ain.z,  16);
    ain.w  += __shfl_xor_sync(0xffffffffu, ain.w,  16);
    aout.x += __shfl_xor_sync(0xffffffffu, aout.x, 16);
    aout.y += __shfl_xor_sync(0xffffffffu, aout.y, 16);
    aout.z += __shfl_xor_sync(0xffffffffu, aout.z, 16);
    aout.w += __shfl_xor_sync(0xffffffffu, aout.w, 16);

    if (half == 0) {
        float di = rsqrtf(1.0f + (float)cA);
        float dq = rsqrtf(1.0f + (float)cB);
        float4 bi = ((const float4*)bin )[fq];
        float4 bo = ((const float4*)bout)[fq];
        float4 r;
        r.x = 0.5f * (aout.x * dq + bo.x) + 0.5f * (ain.x * di + bi.x);
        r.y = 0.5f * (aout.y * dq + bo.y) + 0.5f * (ain.y * di + bi.y);
        r.z = 0.5f * (aout.z * dq + bo.z) + 0.5f * (ain.z * di + bi.z);
        r.w = 0.5f * (aout.w * dq + bo.w) + 0.5f * (ain.w * di + bi.w);
        if (doRelu) {
            r.x = fmaxf(r.x, 0.f); r.y = fmaxf(r.y, 0.f);
            r.z = fmaxf(r.z, 0.f); r.w = fmaxf(r.w, 0.f);
        }
        ((float4*)g_h)[v * 16 + fq] = r;
    }
}

// ---------------- pooling: register accumulation over sorted batch ----------
__global__ void k_pool(const int* __restrict__ batch, int n) {
    __shared__ float sm[NG * F];
    __shared__ float smc[NG];
    int tid = threadIdx.x;                 // 256
    for (int i = tid; i < NG * F; i += 256) sm[i] = 0.f;
    if (tid < NG) smc[tid] = 0.f;
    __syncthreads();

    int per = (n + gridDim.x - 1) / gridDim.x;
    int b0 = blockIdx.x * per;
    int b1 = min(n, b0 + per);

    int f   = tid & 63;
    int sub = tid >> 6;
    {
        float acc = 0.f;
        int curg = -1;
        for (int node = b0 + sub; node < b1; node += 4) {
            int g = batch[node];
            if (g != curg) {
                if (curg >= 0) atomicAdd(&sm[curg * 64 + f], acc);
                acc = 0.f; curg = g;
            }
            acc += g_h[node * 64 + f];
        }
        if (curg >= 0) atomicAdd(&sm[curg * 64 + f], acc);
    }
    for (int node = b0 + tid; node < b1; node += 256)
        atomicAdd(&smc[batch[node]], 1.0f);
    __syncthreads();

    for (int i = tid; i < NG * F; i += 256)
        if (sm[i] != 0.f) atomicAdd(&g_pool[i], sm[i]);
    if (tid < NG && smc[tid] != 0.f) atomicAdd(&g_cnt[tid], smc[tid]);
}

// ---------------- head: mean, LayerNorm, MLP ---------------------------------
__global__ void k_head(const float* __restrict__ lnw, const float* __restrict__ lnb,
                       const float* __restrict__ P1w, const float* __restrict__ P1b,
                       const float* __restrict__ P2w, const float* __restrict__ P2b,
                       float* __restrict__ out) {
    __shared__ float z [NG * F];
    __shared__ float h1[NG * 128];
    int tid = threadIdx.x;           // 128

    if (tid < NG) {
        int g = tid;
        float c = fmaxf(g_cnt[g], 1.0f);
        float inv = 1.0f / c;
        float mu = 0.f;
        for (int f = 0; f < 64; f++) mu += g_pool[g * 64 + f];
        mu *= inv * (1.0f / 64.0f);
        float var = 0.f;
        for (int f = 0; f < 64; f++) {
            float d = g_pool[g * 64 + f] * inv - mu;
            var += d * d;
        }
        var *= (1.0f / 64.0f);
        float rs = rsqrtf(var + 1e-5f);
        for (int f = 0; f < 64; f++)
            z[g * 64 + f] = (g_pool[g * 64 + f] * inv - mu) * rs * lnw[f] + lnb[f];
    }
    __syncthreads();

    for (int idx = tid; idx < NG * 128; idx += 128) {
        int g = idx >> 7, j = idx & 127;
        float s = P1b[j];
        for (int k = 0; k < 64; k++) s += z[g * 64 + k] * P1w[k * 128 + j];
        h1[idx] = fmaxf(s, 0.f);
    }
    __syncthreads();

    {
        int g = tid >> 1, o = tid & 1;
        float s = P2b[o];
        for (int j = 0; j < 128; j++) s += h1[g * 128 + j] * P2w[j * 2 + o];
        out[g * 2 + o] = s;
    }
}

// ---------------- launch -----------------------------------------------------
extern "C" void kernel_launch(void* const* d_in, const int* in_sizes, int n_in,
                              void* d_out, int out_size) {
    const float* x     = (const float*)d_in[0];
    const int*   src   = (const int*)  d_in[1];
    const int*   dst   = (const int*)  d_in[2];
    const int*   batch = (const int*)  d_in[3];
    const float* W1_in = (const float*)d_in[4];
    const float* b1_in = (const float*)d_in[5];
    const float* W1_out= (const float*)d_in[6];
    const float* b1_out= (const float*)d_in[7];
    const float* W2_in = (const float*)d_in[8];
    const float* b2_in = (const float*)d_in[9];
    const float* W2_out= (const float*)d_in[10];
    const float* b2_out= (const float*)d_in[11];
    const float* W3_in = (const float*)d_in[12];
    const float* b3_in = (const float*)d_in[13];
    const float* W3_out= (const float*)d_in[14];
    const float* b3_out= (const float*)d_in[15];
    const float* ln_w  = (const float*)d_in[16];
    const float* ln_b  = (const float*)d_in[17];
    const float* P1_w  = (const float*)d_in[18];
    const float* P1_b  = (const float*)d_in[19];
    const float* P2_w  = (const float*)d_in[20];
    const float* P2_b  = (const float*)d_in[21];
    float* out = (float*)d_out;

    int n = in_sizes[0] / 64;   // 50000
    int e = in_sizes[1];        // 800000

    int ib  = (n + 255) / 256;
    int eb2 = ((e + 1) / 2 + 255) / 256;
    k_init <<<ib, 256>>>(n);
    k_build<<<eb2, 256>>>(src, dst, e);
    k_pad  <<<ib, 256>>>(n);

    int gemmBlocks = (n + 127) / 128;
    int gathBlocks = (n * 32 + 255) / 256;

    // layer 1
    k_gemm  <<<gemmBlocks, 256>>>(x, W1_in, W1_out, n);
    k_gather<<<gathBlocks, 256>>>(b1_in, b1_out, n, 1);
    // layer 2
    k_gemm  <<<gemmBlocks, 256>>>(nullptr, W2_in, W2_out, n);
    k_gather<<<gathBlocks, 256>>>(b2_in, b2_out, n, 1);
    // layer 3
    k_gemm  <<<gemmBlocks, 256>>>(nullptr, W3_in, W3_out, n);
    k_gather<<<gathBlocks, 256>>>(b3_in, b3_out, n, 0);

    k_pool<<<128, 256>>>(batch, n);
    k_head<<<1, 128>>>(ln_w, ln_b, P1_w, P1_b, P2_w, P2_b, out);
}

// round 17
// speedup vs baseline: 1.0174x; 1.0174x over previous
#include <cuda_runtime.h>
#include <cuda_fp16.h>
#include <cstdint>

#define NN 50000
#define EE 800000
#define F  64
#define NG 64
#define CAP 64          // per-node neighbor bucket capacity (max degree ~45, +3 pad)

// ---------------- scratch (device globals) ----------------------------------
__device__ __half g_pinh [(NN + 1) * F];   // row NN = zero row (pad target)
__device__ __half g_pouth[(NN + 1) * F];
__device__ float  g_h    [NN * F];
__device__ float  g_pool [NG * F];
__device__ float  g_cnt  [NG];

__device__ int g_cntin [NN];
__device__ int g_cntout[NN];
__device__ int g_bin [NN * CAP];
__device__ int g_bout[NN * CAP];

__device__ __forceinline__ unsigned h2_as_u(__half2 h) {
    return *reinterpret_cast<unsigned*>(&h);
}
__device__ __forceinline__ __half2 u_as_h2(unsigned u) {
    return *reinterpret_cast<__half2*>(&u);
}
// packed f32x2 FMA: d = a*b + d  (PTX ISA 8.6+, sm_100+)
__device__ __forceinline__ void ffma2(unsigned long long& d,
                                      unsigned long long a, unsigned long long b) {
    asm("fma.rn.f32x2 %0, %1, %2, %0;" : "+l"(d) : "l"(a), "l"(b));
}
__device__ __forceinline__ unsigned long long dup_f32(float x) {
    unsigned long long r;
    asm("mov.b64 %0, {%1, %1};" : "=l"(r) : "f"(x));
    return r;
}
__device__ __forceinline__ float2 unpack_f32x2(unsigned long long v) {
    float2 f;
    asm("mov.b64 {%0, %1}, %2;" : "=f"(f.x), "=f"(f.y) : "l"(v));
    return f;
}

// ---------------- init -------------------------------------------------------
__global__ void k_init(int n) {
    int t = blockIdx.x * blockDim.x + threadIdx.x;
    if (t < n) { g_cntin[t] = 0; g_cntout[t] = 0; }
    if (t < NG * F) g_pool[t] = 0.0f;
    if (t < NG) g_cnt[t] = 0.0f;
    if (t < F) {                         // zero row for bucket padding
        g_pinh [NN * F + t] = __ushort_as_half(0);
        g_pouth[NN * F + t] = __ushort_as_half(0);
    }
}

// ---------------- fused bucket build: 1 pass, rank = atomic return ----------
__global__ void k_build(const int* __restrict__ src, const int* __restrict__ dst, int e) {
    int t = blockIdx.x * blockDim.x + threadIdx.x;
    int i = t * 2;
    if (i + 1 < e) {
        int2 s2 = ((const int2*)src)[t];
        int2 d2 = ((const int2*)dst)[t];
        int r0 = atomicAdd(&g_cntin [d2.x], 1);
        int r1 = atomicAdd(&g_cntin [d2.y], 1);
        int q0 = atomicAdd(&g_cntout[s2.x], 1);
        int q1 = atomicAdd(&g_cntout[s2.y], 1);
        g_bin [d2.x * CAP + r0] = s2.x;
        g_bin [d2.y * CAP + r1] = s2.y;
        g_bout[s2.x * CAP + q0] = d2.x;
        g_bout[s2.y * CAP + q1] = d2.y;
    } else if (i < e) {
        int s = src[i], d = dst[i];
        int r = atomicAdd(&g_cntin [d], 1); g_bin [d * CAP + r] = s;
        int q = atomicAdd(&g_cntout[s], 1); g_bout[s * CAP + q] = d;
    }
}

// ---------------- pad buckets to quad boundary with zero-row index ----------
__global__ void k_pad(int n) {
    int t = blockIdx.x * blockDim.x + threadIdx.x;
    if (t >= n) return;
    int c = g_cntin[t];
    int r = (c + 3) & ~3;
    for (int j = c; j < r; j++) g_bin[t * CAP + j] = NN;
    c = g_cntout[t];
    r = (c + 3) & ~3;
    for (int j = c; j < r; j++) g_bout[t * CAP + j] = NN;
}

// ---------------- fused dual GEMM, f32x2 FFMA, vectorized xs loads (R15) ---
__global__ __launch_bounds__(256) void k_gemm(const float* __restrict__ xin,
                                              const float* __restrict__ Win,
                                              const float* __restrict__ Wout,
                                              int n) {
    __shared__ float xs[64 * 64];
    __shared__ float wi[64 * 64];
    __shared__ float wo[64 * 64];
    const float* x = xin ? xin : g_h;

    int tid = threadIdx.x;
    {
        float4* wi4 = (float4*)wi; const float4* Wi4 = (const float4*)Win;
        float4* wo4 = (float4*)wo; const float4* Wo4 = (const float4*)Wout;
        #pragma unroll
        for (int i = tid; i < 1024; i += 256) { wi4[i] = Wi4[i]; wo4[i] = Wo4[i]; }
    }
    int base = blockIdx.x * 64;
    {
        const float4* x4 = (const float4*)x;
        #pragma unroll
        for (int i = tid; i < 1024; i += 256) {
            int r = i >> 4;
            int row = base + r;
            ((float4*)xs)[i] = (row < n) ? x4[row * 16 + (i & 15)]
                                         : make_float4(0.f, 0.f, 0.f, 0.f);
        }
    }
    __syncthreads();

    int fq = tid & 15;
    int rg = tid >> 4;
    int r0 = rg * 4;

    unsigned long long ai[4][2], ao[4][2];
    #pragma unroll
    for (int r = 0; r < 4; r++) {
        ai[r][0] = 0ull; ai[r][1] = 0ull;
        ao[r][0] = 0ull; ao[r][1] = 0ull;
    }
    const ulonglong2* wi2 = (const ulonglong2*)wi;
    const ulonglong2* wo2 = (const ulonglong2*)wo;
    const float4* xs4 = (const float4*)xs;
    #pragma unroll
    for (int kq = 0; kq < 16; kq++) {
        float4 xa[4];
        #pragma unroll
        for (int r = 0; r < 4; r++) xa[r] = xs4[(r0 + r) * 16 + kq];
        #pragma unroll
        for (int kk = 0; kk < 4; kk++) {
            ulonglong2 wa = wi2[(kq * 4 + kk) * 16 + fq];
            ulonglong2 wb = wo2[(kq * 4 + kk) * 16 + fq];
            #pragma unroll
            for (int r = 0; r < 4; r++) {
                float xv = (kk == 0) ? xa[r].x : (kk == 1) ? xa[r].y
                          : (kk == 2) ? xa[r].z : xa[r].w;
                unsigned long long xk2 = dup_f32(xv);
                ffma2(ai[r][0], xk2, wa.x);
                ffma2(ai[r][1], xk2, wa.y);
                ffma2(ao[r][0], xk2, wb.x);
                ffma2(ao[r][1], xk2, wb.y);
            }
        }
    }
    #pragma unroll
    for (int r = 0; r < 4; r++) {
        int row = base + r0 + r;
        if (row >= n) break;
        float di = rsqrtf(1.0f + (float)g_cntin [row]);
        float dq = rsqrtf(1.0f + (float)g_cntout[row]);
        float2 i01 = unpack_f32x2(ai[r][0]), i23 = unpack_f32x2(ai[r][1]);
        float2 o01 = unpack_f32x2(ao[r][0]), o23 = unpack_f32x2(ao[r][1]);
        __half2 pi0 = __float22half2_rn(make_float2(i01.x * di, i01.y * di));
        __half2 pi1 = __float22half2_rn(make_float2(i23.x * di, i23.y * di));
        __half2 po0 = __float22half2_rn(make_float2(o01.x * dq, o01.y * dq));
        __half2 po1 = __float22half2_rn(make_float2(o23.x * dq, o23.y * dq));
        uint2 ui, uo;
        ui.x = h2_as_u(pi0); ui.y = h2_as_u(pi1);
        uo.x = h2_as_u(po0); uo.y = h2_as_u(po1);
        ((uint2*)g_pinh )[row * 16 + fq] = ui;
        ((uint2*)g_pouth)[row * 16 + fq] = uo;
    }
}

// ---------------- gather: interleaved directions + index prefetch -----------
__global__ __launch_bounds__(256) void k_gather(const float* __restrict__ bin,
                                                const float* __restrict__ bout,
                                                int n, int doRelu) {
    int v = (blockIdx.x * 256 + threadIdx.x) >> 5;
    if (v >= n) return;
    int lane = threadIdx.x & 31;
    int fq   = lane & 15;
    int half = lane >> 4;
    const uint2* pin2  = (const uint2*)g_pinh;
    const uint2* pout2 = (const uint2*)g_pouth;

    __half2 z = u_as_h2(0u);
    __half2 a0x = z, a0y = z, a1x = z, a1y = z;
    __half2 b0x = z, b0y = z, b1x = z, b1y = z;

    if (half == 0) {
        uint2 s = pin2[v * 16 + fq];
        a0x = u_as_h2(s.x); a0y = u_as_h2(s.y);
        uint2 t = pout2[v * 16 + fq];
        b0x = u_as_h2(t.x); b0y = u_as_h2(t.y);
    }

    int cA = g_cntin [v];
    int cB = g_cntout[v];
    const int4* binA = (const int4*)(g_bin  + v * CAP);
    const int4* binB = (const int4*)(g_bout + v * CAP);

    int nqA = (cA + 3) >> 2;
    int nqB = (cB + 3) >> 2;
    int nq  = max(nqA, nqB);

    // prefetch first index quads (warp-uniform loads)
    int4 iA = (nqA > 0) ? binA[0] : make_int4(NN, NN, NN, NN);
    int4 iB = (nqB > 0) ? binB[0] : make_int4(NN, NN, NN, NN);

    for (int j = 0; j < nq; j++) {
        int4 curA = iA, curB = iB;
        // prefetch next quads while current messages load
        if (j + 1 < nqA) iA = binA[j + 1];
        if (j + 1 < nqB) iB = binB[j + 1];

        if (j < nqA) {
            int e0 = half ? curA.y : curA.x;
            int e1 = half ? curA.w : curA.z;
            uint2 m0 = pin2[e0 * 16 + fq];
            uint2 m1 = pin2[e1 * 16 + fq];
            a0x = __hadd2(a0x, u_as_h2(m0.x)); a0y = __hadd2(a0y, u_as_h2(m0.y));
            a1x = __hadd2(a1x, u_as_h2(m1.x)); a1y = __hadd2(a1y, u_as_h2(m1.y));
        }
        if (j < nqB) {
            int e0 = half ? curB.y : curB.x;
            int e1 = half ? curB.w : curB.z;
            uint2 m0 = pout2[e0 * 16 + fq];
            uint2 m1 = pout2[e1 * 16 + fq];
            b0x = __hadd2(b0x, u_as_h2(m0.x)); b0y = __hadd2(b0y, u_as_h2(m0.y));
            b1x = __hadd2(b1x, u_as_h2(m1.x)); b1y = __hadd2(b1y, u_as_h2(m1.y));
        }
    }

    float2 p0, p1;
    float4 ain, aout;
    p0 = __half22float2(a0x); p1 = __half22float2(a1x);
    ain.x = p0.x + p1.x; ain.y = p0.y + p1.y;
    p0 = __half22float2(a0y); p1 = __half22float2(a1y);
    ain.z = p0.x + p1.x; ain.w = p0.y + p1.y;
    p0 = __half22float2(b0x); p1 = __half22float2(b1x);
    aout.x = p0.x + p1.x; aout.y = p0.y + p1.y;
    p0 = __half22float2(b0y); p1 = __half22float2(b1y);
    aout.z = p0.x + p1.x; aout.w = p0.y + p1.y;

    ain.x  += __shfl_xor_sync(0xffffffffu, ain.x,  16);
    ain.y  += __shfl_xor_sync(0xffffffffu, ain.y,  16);
    ain.z  += __shfl_xor_sync(0xffffffffu, ain.z,  16);
    ain.w  += __shfl_xor_sync(0xffffffffu, ain.w,  16);
    aout.x += __shfl_xor_sync(0xffffffffu, aout.x, 16);
    aout.y += __shfl_xor_sync(0xffffffffu, aout.y, 16);
    aout.z += __shfl_xor_sync(0xffffffffu, aout.z, 16);
    aout.w += __shfl_xor_sync(0xffffffffu, aout.w, 16);

    if (half == 0) {
        float di = rsqrtf(1.0f + (float)cA);
        float dq = rsqrtf(1.0f + (float)cB);
        float4 bi = ((const float4*)bin )[fq];
        float4 bo = ((const float4*)bout)[fq];
        float4 r;
        r.x = 0.5f * (aout.x * dq + bo.x) + 0.5f * (ain.x * di + bi.x);
        r.y = 0.5f * (aout.y * dq + bo.y) + 0.5f * (ain.y * di + bi.y);
        r.z = 0.5f * (aout.z * dq + bo.z) + 0.5f * (ain.z * di + bi.z);
        r.w = 0.5f * (aout.w * dq + bo.w) + 0.5f * (ain.w * di + bi.w);
        if (doRelu) {
            r.x = fmaxf(r.x, 0.f); r.y = fmaxf(r.y, 0.f);
            r.z = fmaxf(r.z, 0.f); r.w = fmaxf(r.w, 0.f);
        }
        ((float4*)g_h)[v * 16 + fq] = r;
    }
}

// ---------------- pooling: register accumulation over sorted batch ----------
__global__ void k_pool(const int* __restrict__ batch, int n) {
    __shared__ float sm[NG * F];
    __shared__ float smc[NG];
    int tid = threadIdx.x;                 // 256
    for (int i = tid; i < NG * F; i += 256) sm[i] = 0.f;
    if (tid < NG) smc[tid] = 0.f;
    __syncthreads();

    int per = (n + gridDim.x - 1) / gridDim.x;
    int b0 = blockIdx.x * per;
    int b1 = min(n, b0 + per);

    int f   = tid & 63;
    int sub = tid >> 6;
    {
        float acc = 0.f;
        int curg = -1;
        for (int node = b0 + sub; node < b1; node += 4) {
            int g = batch[node];
            if (g != curg) {
                if (curg >= 0) atomicAdd(&sm[curg * 64 + f], acc);
                acc = 0.f; curg = g;
            }
            acc += g_h[node * 64 + f];
        }
        if (curg >= 0) atomicAdd(&sm[curg * 64 + f], acc);
    }
    for (int node = b0 + tid; node < b1; node += 256)
        atomicAdd(&smc[batch[node]], 1.0f);
    __syncthreads();

    for (int i = tid; i < NG * F; i += 256)
        if (sm[i] != 0.f) atomicAdd(&g_pool[i], sm[i]);
    if (tid < NG && smc[tid] != 0.f) atomicAdd(&g_cnt[tid], smc[tid]);
}

// ---------------- head: mean, LayerNorm, MLP ---------------------------------
__global__ void k_head(const float* __restrict__ lnw, const float* __restrict__ lnb,
                       const float* __restrict__ P1w, const float* __restrict__ P1b,
                       const float* __restrict__ P2w, const float* __restrict__ P2b,
                       float* __restrict__ out) {
    __shared__ float z [NG * F];
    __shared__ float h1[NG * 128];
    int tid = threadIdx.x;           // 128

    if (tid < NG) {
        int g = tid;
        float c = fmaxf(g_cnt[g], 1.0f);
        float inv = 1.0f / c;
        float mu = 0.f;
        for (int f = 0; f < 64; f++) mu += g_pool[g * 64 + f];
        mu *= inv * (1.0f / 64.0f);
        float var = 0.f;
        for (int f = 0; f < 64; f++) {
            float d = g_pool[g * 64 + f] * inv - mu;
            var += d * d;
        }
        var *= (1.0f / 64.0f);
        float rs = rsqrtf(var + 1e-5f);
        for (int f = 0; f < 64; f++)
            z[g * 64 + f] = (g_pool[g * 64 + f] * inv - mu) * rs * lnw[f] + lnb[f];
    }
    __syncthreads();

    for (int idx = tid; idx < NG * 128; idx += 128) {
        int g = idx >> 7, j = idx & 127;
        float s = P1b[j];
        for (int k = 0; k < 64; k++) s += z[g * 64 + k] * P1w[k * 128 + j];
        h1[idx] = fmaxf(s, 0.f);
    }
    __syncthreads();

    {
        int g = tid >> 1, o = tid & 1;
        float s = P2b[o];
        for (int j = 0; j < 128; j++) s += h1[g * 128 + j] * P2w[j * 2 + o];
        out[g * 2 + o] = s;
    }
}

// ---------------- launch -----------------------------------------------------
extern "C" void kernel_launch(void* const* d_in, const int* in_sizes, int n_in,
                              void* d_out, int out_size) {
    const float* x     = (const float*)d_in[0];
    const int*   src   = (const int*)  d_in[1];
    const int*   dst   = (const int*)  d_in[2];
    const int*   batch = (const int*)  d_in[3];
    const float* W1_in = (const float*)d_in[4];
    const float* b1_in = (const float*)d_in[5];
    const float* W1_out= (const float*)d_in[6];
    const float* b1_out= (const float*)d_in[7];
    const float* W2_in = (const float*)d_in[8];
    const float* b2_in = (const float*)d_in[9];
    const float* W2_out= (const float*)d_in[10];
    const float* b2_out= (const float*)d_in[11];
    const float* W3_in = (const float*)d_in[12];
    const float* b3_in = (const float*)d_in[13];
    const float* W3_out= (const float*)d_in[14];
    const float* b3_out= (const float*)d_in[15];
    const float* ln_w  = (const float*)d_in[16];
    const float* ln_b  = (const float*)d_in[17];
    const float* P1_w  = (const float*)d_in[18];
    const float* P1_b  = (const float*)d_in[19];
    const float* P2_w  = (const float*)d_in[20];
    const float* P2_b  = (const float*)d_in[21];
    float* out = (float*)d_out;

    int n = in_sizes[0] / 64;   // 50000
    int e = in_sizes[1];        // 800000

    int ib  = (n + 255) / 256;
    int eb2 = ((e + 1) / 2 + 255) / 256;
    k_init <<<ib, 256>>>(n);
    k_build<<<eb2, 256>>>(src, dst, e);
    k_pad  <<<ib, 256>>>(n);

    int gemmBlocks = (n + 63) / 64;
    int gathBlocks = (n * 32 + 255) / 256;

    // layer 1
    k_gemm  <<<gemmBlocks, 256>>>(x, W1_in, W1_out, n);
    k_gather<<<gathBlocks, 256>>>(b1_in, b1_out, n, 1);
    // layer 2
    k_gemm  <<<gemmBlocks, 256>>>(nullptr, W2_in, W2_out, n);
    k_gather<<<gathBlocks, 256>>>(b2_in, b2_out, n, 1);
    // layer 3
    k_gemm  <<<gemmBlocks, 256>>>(nullptr, W3_in, W3_out, n);
    k_gather<<<gathBlocks, 256>>>(b3_in, b3_out, n, 0);

    k_pool<<<128, 256>>>(batch, n);
    k_head<<<1, 128>>>(ln_w, ln_b, P1_w, P1_b, P2_w, P2_b, out);
}